// round 16
// baseline (speedup 1.0000x reference)
#include <cuda_runtime.h>
#include <cstdint>

// TopK-magnitude masking per row. x: (4096, 8192) fp32, K = 819.
// out[r,c] = x[r,c] if |x[r,c]| >= (K-th largest |x| in row r) else 0.
//
// Bracketed exact select (rows ~ N(0,1): the 819th largest |x| lies in
// [1.5, 1.8] with ~9-sigma margins). TPB=256, 32 elems/thread, 8 CTAs/SM for
// phase staggering. ONE fused sweep writes final output for decided elements
// (register-only bookkeeping), a block scan compacts the ~505 bracket
// candidates, ONE 2048-bin radix pass narrows to a bin of 1-3 keys, and
// warp 0 resolves the exact K-th key serially. Scattered fixup zeroes
// bracket losers. CTA-uniform fallbacks (big bin -> pass-B scan; bracket
// violated -> full 3-pass radix) keep the kernel exact for ANY input.

#define ROWLEN  8192
#define TPB     256
#define NW      (TPB / 32)     // 8 warps
#define KSEL    819u
#define CANDMAX 1024
#define BINMAX  64
#define KA      0x3FC00000u    // bits(1.5f)
#define KB      0x3FE66666u    // bits(1.8f)

// Suffix-scan + digit select over h[NB] (B = NB/TPB bins per thread).
// Outputs *sh_digit, *sh_k (rank within digit), *sh_cnt (digit count).
// Ends with __syncthreads.
template <int NB>
__device__ __forceinline__ void suffix_select(
    const unsigned* __restrict__ h, unsigned k,
    int t, int lane, int wid,
    unsigned* wsum, unsigned* wtail,
    unsigned* sh_digit, unsigned* sh_k, unsigned* sh_cnt)
{
    constexpr int B = NB / TPB;
    const int base = t * B;
    unsigned loc[B];
    unsigned s = 0u;
#pragma unroll
    for (int j = B - 1; j >= 0; j--) { s += h[base + j]; loc[j] = s; }
    unsigned p = s;                        // warp suffix scan of chunk totals
#pragma unroll
    for (int off = 1; off < 32; off <<= 1) {
        unsigned n = __shfl_down_sync(0xFFFFFFFFu, p, off);
        if (lane < 32 - off) p += n;
    }
    if (lane == 0) wsum[wid] = p;
    __syncthreads();
    if (t < NW) {
        unsigned q = wsum[t];
        unsigned r = q;
#pragma unroll
        for (int off = 1; off < NW; off <<= 1) {
            unsigned n = __shfl_down_sync((unsigned)((1u << NW) - 1u), r, off);
            if (t < NW - off) r += n;
        }
        wtail[t] = r - q;                  // total of warps AFTER warp t
    }
    __syncthreads();
    unsigned beyond = (p - s) + wtail[wid];
#pragma unroll
    for (int j = 0; j < B; j++) {
        unsigned incl = loc[j] + beyond;                          // count(>=d)
        unsigned cnt  = loc[j] - ((j < B - 1) ? loc[j + 1] : 0u); // hist[d]
        unsigned gt   = incl - cnt;                               // count(>d)
        if (incl >= k && gt < k) {
            *sh_digit = (unsigned)(base + j);
            *sh_k     = k - gt;
            *sh_cnt   = cnt;
        }
    }
    __syncthreads();
}

__global__ __launch_bounds__(TPB, 8)
void topk_mask_kernel(const float* __restrict__ x, float* __restrict__ out) {
    __shared__ unsigned       hist[2048];        // 8 KB
    __shared__ unsigned       ck[CANDMAX];       // 4 KB  candidate keys
    __shared__ unsigned short cpos[CANDMAX];     // 2 KB  candidate positions
    __shared__ unsigned       kbin[BINMAX];      // keys in the threshold bin
    __shared__ unsigned       wsum[NW], wtail[NW], whi[NW], wbase[NW];
    __shared__ unsigned       sh_digit, sh_k, sh_cnt, sh_cc, sh_hi, sh_T, bcnt;

    const int t    = threadIdx.x;
    const int lane = t & 31;
    const int wid  = t >> 5;
    const size_t row_off = (size_t)blockIdx.x * ROWLEN;
    const unsigned* __restrict__ pxs  = reinterpret_cast<const unsigned*>(x + row_off);
    const uint4*    __restrict__ px   = reinterpret_cast<const uint4*>(x + row_off);
    uint4*          __restrict__ po   = reinterpret_cast<uint4*>(out + row_off);
    float*          __restrict__ pout = out + row_off;

    // ---- zero pass-A histogram (2048 words = 2 uint4/thread) ----
    {
        uint4 z = make_uint4(0u, 0u, 0u, 0u);
        uint4* h4 = reinterpret_cast<uint4*>(hist);
        h4[t] = z; h4[t + TPB] = z;
        if (t == 0) bcnt = 0u;
    }
    __syncthreads();

    // ---- fused sweep: load -> final store + register-only bookkeeping ----
    unsigned cmask = 0u;     // bit i*4+c set if element in [1.5, 1.8]
    unsigned myhi  = 0u;     // count of |x| > 1.8
#pragma unroll
    for (int i = 0; i < 8; i++) {
        uint4 a = px[t + i * TPB];
        const unsigned b[4] = {a.x, a.y, a.z, a.w};
        unsigned o[4];
#pragma unroll
        for (int c = 0; c < 4; c++) {
            unsigned key = b[c] & 0x7FFFFFFFu;
            bool lo = (key < KA);
            bool hi = (key > KB);
            o[c] = lo ? 0u : b[c];            // decided or provisional keep
            myhi += hi;
            if (!lo && !hi) cmask |= 1u << (i * 4 + c);
        }
        po[t + i * TPB] = make_uint4(o[0], o[1], o[2], o[3]);
    }
    const unsigned cnt = (unsigned)__popc(cmask);

    // ---- block scan of candidate counts + block reduce of hi counts ----
    unsigned inc = cnt;                     // warp inclusive scan
#pragma unroll
    for (int off = 1; off < 32; off <<= 1) {
        unsigned n = __shfl_up_sync(0xFFFFFFFFu, inc, off);
        if (lane >= off) inc += n;
    }
    {
        unsigned h = myhi;                  // warp reduce
#pragma unroll
        for (int off = 16; off >= 1; off >>= 1)
            h += __shfl_down_sync(0xFFFFFFFFu, h, off);
        if (lane == 31) wsum[wid] = inc;
        if (lane == 0)  whi[wid]  = h;
    }
    __syncthreads();
    if (t < NW) {
        unsigned q = wsum[t];
        unsigned e = q;                     // inclusive scan over 8 warps
#pragma unroll
        for (int off = 1; off < NW; off <<= 1) {
            unsigned n = __shfl_up_sync(0x000000FFu, e, off);
            if (t >= off) e += n;
        }
        wbase[t] = e - q;                   // exclusive base for warp t
        if (t == NW - 1) sh_cc = e;         // total candidates
        unsigned hh = whi[t];
#pragma unroll
        for (int off = NW / 2; off >= 1; off >>= 1)
            hh += __shfl_down_sync(0x000000FFu, hh, off);
        if (t == 0) sh_hi = hh;
    }
    __syncthreads();

    const unsigned HI = sh_hi;
    const unsigned CC = sh_cc;

    // ---- sparse candidate write (~2 iterations/thread) ----
    if (CC <= CANDMAX) {
        unsigned off = wbase[wid] + inc - cnt;   // exclusive global offset
        unsigned m = cmask;
        while (m) {
            const int idx = __ffs(m) - 1;
            m &= m - 1u;
            const int pos = 4 * t + (idx & 3) + 1024 * (idx >> 2);
            ck[off]   = pxs[pos] & 0x7FFFFFFFu;  // L1/L2-hot re-read
            cpos[off] = (unsigned short)pos;
            off++;
        }
    }
    __syncthreads();

    const bool fast = (HI < KSEL) && (CC <= CANDMAX) && (HI + CC >= KSEL);

    if (fast) {
        unsigned k = KSEL - HI;            // rank among candidates

        // ---- pass A: mantissa bits [11,22), 2048 bins, ~2 cand/thread ----
        for (unsigned j = t; j < CC; j += TPB)
            atomicAdd(&hist[(ck[j] >> 11) & 0x7FFu], 1u);
        __syncthreads();
        suffix_select<2048>(hist, k, t, lane, wid, wsum, wtail,
                            &sh_digit, &sh_k, &sh_cnt);
        const unsigned dA   = sh_digit;
        const unsigned binc = sh_cnt;      // candidates in threshold bin
        k = sh_k;

        if (binc <= BINMAX) {
            // ---- gather the bin's keys (1-3 typical) + warp-0 resolve ----
            for (unsigned j = t; j < CC; j += TPB) {
                unsigned kk = ck[j];
                if (((kk >> 11) & 0x7FFu) == dA)
                    kbin[atomicAdd(&bcnt, 1u)] = kk;
            }
            __syncthreads();
            if (wid == 0 && lane < (int)binc) {
                unsigned kl = kbin[lane];
                unsigned gt = 0u, eq = 0u;
                for (unsigned j = 0; j < binc; j++) {
                    unsigned kj = kbin[j];
                    gt += (kj > kl);
                    eq += (kj == kl);
                }
                if (gt < k && k <= gt + eq) sh_T = kl;  // exact K-th key
            }
            __syncthreads();
        } else {
            // rare: big bin -> pass-B radix over low 11 bits
            uint4 z = make_uint4(0u, 0u, 0u, 0u);
            uint4* h4 = reinterpret_cast<uint4*>(hist);
            h4[t] = z; h4[t + TPB] = z;
            __syncthreads();
            for (unsigned j = t; j < CC; j += TPB) {
                unsigned kk = ck[j];
                if (((kk >> 11) & 0x7FFu) == dA)
                    atomicAdd(&hist[kk & 0x7FFu], 1u);
            }
            __syncthreads();
            suffix_select<2048>(hist, k, t, lane, wid, wsum, wtail,
                                &sh_digit, &sh_k, &sh_cnt);
            if (t == 0) sh_T = (KA & 0xFFC00000u) | (dA << 11) | sh_digit;
            __syncthreads();
        }
        const unsigned T = sh_T;

        // ---- fixup: zero bracket losers (scattered ~250 stores/row) ----
        for (unsigned j = t; j < CC; j += TPB)
            if (ck[j] < T)
                pout[cpos[j]] = 0.0f;
    } else {
        // ======== exact fallback: full 3-pass radix (11+10+10) from x ======
        unsigned k = KSEL;
        uint4 z = make_uint4(0u, 0u, 0u, 0u);
        uint4* h4 = reinterpret_cast<uint4*>(hist);

        h4[t] = z; h4[t + TPB] = z;
        __syncthreads();
#pragma unroll
        for (int i = 0; i < 8; i++) {
            uint4 a = px[t + i * TPB];
            const unsigned b[4] = {a.x, a.y, a.z, a.w};
#pragma unroll
            for (int c = 0; c < 4; c++)
                atomicAdd(&hist[(b[c] & 0x7FFFFFFFu) >> 20], 1u);
        }
        __syncthreads();
        suffix_select<2048>(hist, k, t, lane, wid, wsum, wtail,
                            &sh_digit, &sh_k, &sh_cnt);
        const unsigned d1 = sh_digit; k = sh_k;

        h4[t] = z; h4[t + TPB] = z;
        __syncthreads();
#pragma unroll
        for (int i = 0; i < 8; i++) {
            uint4 a = px[t + i * TPB];
            const unsigned b[4] = {a.x, a.y, a.z, a.w};
#pragma unroll
            for (int c = 0; c < 4; c++) {
                unsigned kk = b[c] & 0x7FFFFFFFu;
                if ((kk >> 20) == d1)
                    atomicAdd(&hist[(kk >> 10) & 0x3FFu], 1u);
            }
        }
        __syncthreads();
        suffix_select<1024>(hist, k, t, lane, wid, wsum, wtail,
                            &sh_digit, &sh_k, &sh_cnt);
        const unsigned d2 = sh_digit; k = sh_k;
        const unsigned pref21 = (d1 << 10) | d2;

        h4[t] = z; h4[t + TPB] = z;
        __syncthreads();
#pragma unroll
        for (int i = 0; i < 8; i++) {
            uint4 a = px[t + i * TPB];
            const unsigned b[4] = {a.x, a.y, a.z, a.w};
#pragma unroll
            for (int c = 0; c < 4; c++) {
                unsigned kk = b[c] & 0x7FFFFFFFu;
                if ((kk >> 10) == pref21)
                    atomicAdd(&hist[kk & 0x3FFu], 1u);
            }
        }
        __syncthreads();
        suffix_select<1024>(hist, k, t, lane, wid, wsum, wtail,
                            &sh_digit, &sh_k, &sh_cnt);
        const unsigned T = (pref21 << 10) | sh_digit;

        // full exact re-store
#pragma unroll
        for (int i = 0; i < 8; i++) {
            uint4 a = px[t + i * TPB];
            const unsigned b[4] = {a.x, a.y, a.z, a.w};
            unsigned o[4];
#pragma unroll
            for (int c = 0; c < 4; c++) {
                unsigned kk = b[c] & 0x7FFFFFFFu;
                o[c] = (kk < T) ? 0u : b[c];
            }
            po[t + i * TPB] = make_uint4(o[0], o[1], o[2], o[3]);
        }
    }
}

extern "C" void kernel_launch(void* const* d_in, const int* in_sizes, int n_in,
                              void* d_out, int out_size) {
    const float* x = (const float*)d_in[0];
    float* out = (float*)d_out;
    const int rows = in_sizes[0] / ROWLEN;   // 4096
    topk_mask_kernel<<<rows, TPB>>>(x, out);
}

// round 17
// speedup vs baseline: 1.9812x; 1.9812x over previous
#include <cuda_runtime.h>
#include <cstdint>

// TopK-magnitude masking per row. x: (4096, 8192) fp32, K = 819.
// out[r,c] = x[r,c] if |x[r,c]| >= (K-th largest |x| in row r) else 0.
//
// Bracketed exact select + cross-row cp.async pipeline.
// grid=1024 CTAs x 4 rows each, TPB=512, 4 CTAs/SM. Row r+GRIDN streams into
// the smem row buffer via cp.async WHILE row r's select/fixup runs, keeping
// DRAM busy through the barrier-heavy select phase. The row buffer also
// serves candidate compaction (smem reads; no scattered global re-reads).
// Select: one fused sweep (final store + register bookkeeping), block-scan
// compaction of ~505 bracket candidates, ONE 2048-bin radix pass, warp-0
// exact resolve of the 1-3-key threshold bin, scattered smem-indexed fixup.
// CTA-uniform exact fallbacks (big bin -> pass-B; bracket violated -> full
// 3-pass radix from the smem buffer) keep it correct for ANY input.

#define ROWLEN  8192
#define TPB     512
#define NW      16
#define GRIDN   1024
#define NROWS   4096
#define NITER   (NROWS / GRIDN)   // 4 rows per CTA
#define KSEL    819u
#define CANDMAX 1024
#define BINMAX  32
#define KA      0x3FC00000u       // bits(1.5f)
#define KB      0x3FE66666u       // bits(1.8f)

__device__ __forceinline__ void prefetch_row(float* buf, const float* src, int t) {
#pragma unroll
    for (int i = 0; i < 4; i++) {
        unsigned sa = (unsigned)__cvta_generic_to_shared(buf + 4 * (t + i * TPB));
        asm volatile("cp.async.cg.shared.global [%0], [%1], 16;"
                     :: "r"(sa), "l"(src + 4 * (t + i * TPB)));
    }
    asm volatile("cp.async.commit_group;" ::: "memory");
}

// Suffix-scan + digit select over h[NB] (B = NB/TPB bins per thread).
// Outputs *sh_digit, *sh_k (rank within digit), *sh_cnt (digit count).
// Ends with __syncthreads.
template <int NB>
__device__ __forceinline__ void suffix_select(
    const unsigned* __restrict__ h, unsigned k,
    int t, int lane, int wid,
    unsigned* wsum, unsigned* wtail,
    unsigned* sh_digit, unsigned* sh_k, unsigned* sh_cnt)
{
    constexpr int B = NB / TPB;
    const int base = t * B;
    unsigned loc[B];
    unsigned s = 0u;
#pragma unroll
    for (int j = B - 1; j >= 0; j--) { s += h[base + j]; loc[j] = s; }
    unsigned p = s;                        // warp suffix scan of chunk totals
#pragma unroll
    for (int off = 1; off < 32; off <<= 1) {
        unsigned n = __shfl_down_sync(0xFFFFFFFFu, p, off);
        if (lane < 32 - off) p += n;
    }
    if (lane == 0) wsum[wid] = p;
    __syncthreads();
    if (t < NW) {
        unsigned q = wsum[t];
        unsigned r = q;
#pragma unroll
        for (int off = 1; off < NW; off <<= 1) {
            unsigned n = __shfl_down_sync(0x0000FFFFu, r, off);
            if (t < NW - off) r += n;
        }
        wtail[t] = r - q;                  // total of warps AFTER warp t
    }
    __syncthreads();
    unsigned beyond = (p - s) + wtail[wid];
#pragma unroll
    for (int j = 0; j < B; j++) {
        unsigned incl = loc[j] + beyond;                          // count(>=d)
        unsigned cnt  = loc[j] - ((j < B - 1) ? loc[j + 1] : 0u); // hist[d]
        unsigned gt   = incl - cnt;                               // count(>d)
        if (incl >= k && gt < k) {
            *sh_digit = (unsigned)(base + j);
            *sh_k     = k - gt;
            *sh_cnt   = cnt;
        }
    }
    __syncthreads();
}

__global__ __launch_bounds__(TPB, 4)
void topk_mask_kernel(const float* __restrict__ x, float* __restrict__ out) {
    __shared__ float          buf[ROWLEN];       // 32 KB row buffer
    __shared__ unsigned       hist[2048];        // 8 KB
    __shared__ unsigned       ck[CANDMAX];       // 4 KB candidate keys
    __shared__ unsigned short cpos[CANDMAX];     // 2 KB candidate positions
    __shared__ unsigned       kbin[BINMAX];
    __shared__ unsigned       wsum[NW], wtail[NW], whi[NW], wbase[NW];
    __shared__ unsigned       sh_digit, sh_k, sh_cnt, sh_cc, sh_hi, sh_T, bcnt;

    const int t    = threadIdx.x;
    const int lane = t & 31;
    const int wid  = t >> 5;
    const uint4*    bufv = reinterpret_cast<const uint4*>(buf);
    const unsigned* bufu = reinterpret_cast<const unsigned*>(buf);

    int row = blockIdx.x;
    prefetch_row(buf, x + (size_t)row * ROWLEN, t);   // prologue

    for (int iter = 0; iter < NITER; iter++, row += GRIDN) {
        asm volatile("cp.async.wait_group 0;" ::: "memory");
        __syncthreads();                             // buf holds current row

        uint4*  po   = reinterpret_cast<uint4*>(out + (size_t)row * ROWLEN);
        float*  pout = out + (size_t)row * ROWLEN;

        // ---- zero hist (2048 words = 1 uint4/thread) + bin counter ----
        reinterpret_cast<uint4*>(hist)[t] = make_uint4(0u, 0u, 0u, 0u);
        if (t == 0) bcnt = 0u;

        // ---- fused sweep from smem: final store + register bookkeeping ----
        unsigned cmask = 0u;      // bit i*4+c: element in [1.5, 1.8]
        unsigned myhi  = 0u;      // count |x| > 1.8
#pragma unroll
        for (int i = 0; i < 4; i++) {
            uint4 a = bufv[t + i * TPB];
            const unsigned b[4] = {a.x, a.y, a.z, a.w};
            unsigned o[4];
#pragma unroll
            for (int c = 0; c < 4; c++) {
                unsigned key = b[c] & 0x7FFFFFFFu;
                bool lo = (key < KA);
                bool hi = (key > KB);
                o[c] = lo ? 0u : b[c];
                myhi += hi;
                if (!lo && !hi) cmask |= 1u << (i * 4 + c);
            }
            po[t + i * TPB] = make_uint4(o[0], o[1], o[2], o[3]);
        }
        const unsigned cnt = (unsigned)__popc(cmask);

        // ---- block scan (cand counts) + block reduce (hi counts) ----
        unsigned inc = cnt;
#pragma unroll
        for (int off = 1; off < 32; off <<= 1) {
            unsigned n = __shfl_up_sync(0xFFFFFFFFu, inc, off);
            if (lane >= off) inc += n;
        }
        {
            unsigned h = myhi;
#pragma unroll
            for (int off = 16; off >= 1; off >>= 1)
                h += __shfl_down_sync(0xFFFFFFFFu, h, off);
            if (lane == 31) wsum[wid] = inc;
            if (lane == 0)  whi[wid]  = h;
        }
        __syncthreads();
        if (t < NW) {
            unsigned q = wsum[t];
            unsigned e = q;
#pragma unroll
            for (int off = 1; off < NW; off <<= 1) {
                unsigned n = __shfl_up_sync(0x0000FFFFu, e, off);
                if (t >= off) e += n;
            }
            wbase[t] = e - q;
            if (t == NW - 1) sh_cc = e;
            unsigned hh = whi[t];
#pragma unroll
            for (int off = NW / 2; off >= 1; off >>= 1)
                hh += __shfl_down_sync(0x0000FFFFu, hh, off);
            if (t == 0) sh_hi = hh;
        }
        __syncthreads();

        const unsigned HI = sh_hi;
        const unsigned CC = sh_cc;

        // ---- sparse candidate write from smem buf (~1 iter/thread) ----
        if (CC <= CANDMAX) {
            unsigned off = wbase[wid] + inc - cnt;
            unsigned m = cmask;
            while (m) {
                const int idx = __ffs(m) - 1;
                m &= m - 1u;
                const int pos = 4 * t + (idx & 3) + 2048 * (idx >> 2);
                ck[off]   = bufu[pos] & 0x7FFFFFFFu;
                cpos[off] = (unsigned short)pos;
                off++;
            }
        }
        __syncthreads();                 // all reads of buf complete

        const bool fast = (HI < KSEL) && (CC <= CANDMAX) && (HI + CC >= KSEL);
        const bool more = (iter + 1 < NITER);

        if (fast) {
            // prefetch next row NOW -> overlaps the whole select phase
            if (more) prefetch_row(buf, x + (size_t)(row + GRIDN) * ROWLEN, t);

            unsigned k = KSEL - HI;

            // ---- pass A: mantissa bits [11,22), 2048 bins ----
            for (unsigned j = t; j < CC; j += TPB)
                atomicAdd(&hist[(ck[j] >> 11) & 0x7FFu], 1u);
            __syncthreads();
            suffix_select<2048>(hist, k, t, lane, wid, wsum, wtail,
                                &sh_digit, &sh_k, &sh_cnt);
            const unsigned dA   = sh_digit;
            const unsigned binc = sh_cnt;
            k = sh_k;

            if (binc <= BINMAX) {
                // gather bin keys (1-3 typical); warp 0 resolves exact k-th
                for (unsigned j = t; j < CC; j += TPB) {
                    unsigned kk = ck[j];
                    if (((kk >> 11) & 0x7FFu) == dA)
                        kbin[atomicAdd(&bcnt, 1u)] = kk;
                }
                __syncthreads();
                if (wid == 0 && lane < (int)binc) {
                    unsigned kl = kbin[lane];
                    unsigned gt = 0u, eq = 0u;
                    for (unsigned j = 0; j < binc; j++) {
                        unsigned kj = kbin[j];
                        gt += (kj > kl);
                        eq += (kj == kl);
                    }
                    if (gt < k && k <= gt + eq) sh_T = kl;
                }
                __syncthreads();
            } else {
                // rare big bin: pass-B radix over low 11 bits
                reinterpret_cast<uint4*>(hist)[t] = make_uint4(0u, 0u, 0u, 0u);
                __syncthreads();
                for (unsigned j = t; j < CC; j += TPB) {
                    unsigned kk = ck[j];
                    if (((kk >> 11) & 0x7FFu) == dA)
                        atomicAdd(&hist[kk & 0x7FFu], 1u);
                }
                __syncthreads();
                suffix_select<2048>(hist, k, t, lane, wid, wsum, wtail,
                                    &sh_digit, &sh_k, &sh_cnt);
                if (t == 0) sh_T = (KA & 0xFFC00000u) | (dA << 11) | sh_digit;
                __syncthreads();
            }
            const unsigned T = sh_T;

            // ---- fixup: zero bracket losers (L2-hot lines) ----
            for (unsigned j = t; j < CC; j += TPB)
                if (ck[j] < T)
                    pout[cpos[j]] = 0.0f;
        } else {
            // ===== exact fallback: full 3-pass radix from smem buf =====
            unsigned k = KSEL;
            // hist already zeroed this iteration and unused since
            __syncthreads();
#pragma unroll
            for (int i = 0; i < 4; i++) {
                uint4 a = bufv[t + i * TPB];
                const unsigned b[4] = {a.x, a.y, a.z, a.w};
#pragma unroll
                for (int c = 0; c < 4; c++)
                    atomicAdd(&hist[(b[c] & 0x7FFFFFFFu) >> 20], 1u);
            }
            __syncthreads();
            suffix_select<2048>(hist, k, t, lane, wid, wsum, wtail,
                                &sh_digit, &sh_k, &sh_cnt);
            const unsigned d1 = sh_digit; k = sh_k;

            reinterpret_cast<uint4*>(hist)[t] = make_uint4(0u, 0u, 0u, 0u);
            __syncthreads();
#pragma unroll
            for (int i = 0; i < 4; i++) {
                uint4 a = bufv[t + i * TPB];
                const unsigned b[4] = {a.x, a.y, a.z, a.w};
#pragma unroll
                for (int c = 0; c < 4; c++) {
                    unsigned kk = b[c] & 0x7FFFFFFFu;
                    if ((kk >> 20) == d1)
                        atomicAdd(&hist[(kk >> 10) & 0x3FFu], 1u);
                }
            }
            __syncthreads();
            suffix_select<1024>(hist, k, t, lane, wid, wsum, wtail,
                                &sh_digit, &sh_k, &sh_cnt);
            const unsigned d2 = sh_digit; k = sh_k;
            const unsigned pref21 = (d1 << 10) | d2;

            reinterpret_cast<uint4*>(hist)[t] = make_uint4(0u, 0u, 0u, 0u);
            __syncthreads();
#pragma unroll
            for (int i = 0; i < 4; i++) {
                uint4 a = bufv[t + i * TPB];
                const unsigned b[4] = {a.x, a.y, a.z, a.w};
#pragma unroll
                for (int c = 0; c < 4; c++) {
                    unsigned kk = b[c] & 0x7FFFFFFFu;
                    if ((kk >> 10) == pref21)
                        atomicAdd(&hist[kk & 0x3FFu], 1u);
                }
            }
            __syncthreads();
            suffix_select<1024>(hist, k, t, lane, wid, wsum, wtail,
                                &sh_digit, &sh_k, &sh_cnt);
            const unsigned T = (pref21 << 10) | sh_digit;

            // exact re-store from buf
#pragma unroll
            for (int i = 0; i < 4; i++) {
                uint4 a = bufv[t + i * TPB];
                const unsigned b[4] = {a.x, a.y, a.z, a.w};
                unsigned o[4];
#pragma unroll
                for (int c = 0; c < 4; c++) {
                    unsigned kk = b[c] & 0x7FFFFFFFu;
                    o[c] = (kk < T) ? 0u : b[c];
                }
                po[t + i * TPB] = make_uint4(o[0], o[1], o[2], o[3]);
            }
            __syncthreads();             // buf reads done before prefetch
            if (more) prefetch_row(buf, x + (size_t)(row + GRIDN) * ROWLEN, t);
        }
    }
}

extern "C" void kernel_launch(void* const* d_in, const int* in_sizes, int n_in,
                              void* d_out, int out_size) {
    const float* x = (const float*)d_in[0];
    float* out = (float*)d_out;
    topk_mask_kernel<<<GRIDN, TPB>>>(x, out);
}